// round 13
// baseline (speedup 1.0000x reference)
#include <cuda_runtime.h>
#include <cuda_bf16.h>

// ---------------------------------------------------------------------------
// AIMNet2 interaction module — fused per-atom formulation.
//
//   radial[i]   = Σ_{p∈i} f_p * A[j_p]
//   s[i,c,:]    = Σ_{p∈i} (f_p u[p,c]) * A[j_p]
//   vec[i,c,:]  = W @ s[i,c,:] + deg(i)*b
//   out[i]      = [ sqrt(Σ_c vec² + 1e-12), radial ]
//
// Pipeline: hist -> parallel 2-phase scan -> scatter (writes SORTED pair meta
//   {f, f*ux, f*uy, f*uz} + j) -> fused kernel (warp = 2 atoms: streaming
//   gather with depth-3 prefetch, then packed-f32x2 matvec, W pre-packed in
//   smem as g-pairs).
// ---------------------------------------------------------------------------

#define FDIM 128
#define MAX_ATOMS 20480
#define MAX_PAIRS 393216
#define CHUNK 2
#define MAIN_BLOCKS 296
#define WARPS_PER_BLOCK 8
#define MAIN_THREADS (WARPS_PER_BLOCK * 32)

typedef unsigned int u32;
typedef unsigned long long ull;

__device__ int g_count[MAX_ATOMS + 1];
__device__ int g_start[MAX_ATOMS + 1];
__device__ int g_cursor[MAX_ATOMS + 1];
__device__ int g_btot[64];
__device__ int g_j[MAX_PAIRS];
__device__ __align__(16) float4 g_meta[MAX_PAIRS];   // {f, f*ux, f*uy, f*uz}

__device__ __forceinline__ ull dup2(float v) {
    ull d; asm("mov.b64 %0, {%1, %1};" : "=l"(d) : "f"(v)); return d;
}
__device__ __forceinline__ ull pack2(float lo, float hi) {
    ull d; asm("mov.b64 %0, {%1, %2};" : "=l"(d) : "f"(lo), "f"(hi)); return d;
}
__device__ __forceinline__ void unpack2(ull v, float& lo, float& hi) {
    asm("mov.b64 {%0, %1}, %2;" : "=f"(lo), "=f"(hi) : "l"(v));
}
#define FMA2(acc, a, b) \
    asm("fma.rn.f32x2 %0, %1, %2, %0;" : "+l"(acc) : "l"(a), "l"(b))

// ---------------------------------------------------------------------------
__global__ void zero_counts_kernel(int n_atoms) {
    int i = blockIdx.x * blockDim.x + threadIdx.x;
    if (i <= n_atoms) g_count[i] = 0;
}

__global__ void hist_kernel(const int* __restrict__ pl, int n_pairs) {
    int p = blockIdx.x * blockDim.x + threadIdx.x;
    if (p < n_pairs) atomicAdd(&g_count[pl[p]], 1);
}

// Phase A: each block scans its 1024-element tile -> local-exclusive values
// in g_start, block total in g_btot.  n = n_atoms+1 (count[n_atoms]=0).
__global__ void scanA_kernel(int n) {
    __shared__ int wsum[32];
    const int tid = threadIdx.x;
    const int lane = tid & 31;
    const int w = tid >> 5;
    const int idx = blockIdx.x * 1024 + tid;
    int v = (idx < n) ? g_count[idx] : 0;
    int incl = v;
    #pragma unroll
    for (int off = 1; off < 32; off <<= 1) {
        int t = __shfl_up_sync(0xffffffffu, incl, off);
        if (lane >= off) incl += t;
    }
    if (lane == 31) wsum[w] = incl;
    __syncthreads();
    if (w == 0) {
        int s = wsum[lane];
        int i2 = s;
        #pragma unroll
        for (int off = 1; off < 32; off <<= 1) {
            int t = __shfl_up_sync(0xffffffffu, i2, off);
            if (lane >= off) i2 += t;
        }
        wsum[lane] = i2 - s;   // exclusive warp offset
    }
    __syncthreads();
    int excl = wsum[w] + incl - v;
    if (idx < n) g_start[idx] = excl;
    if (tid == 1023) g_btot[blockIdx.x] = wsum[w] + incl;
}

// Phase B/C fused: warp-scan the (<=32) block totals, add this block's
// offset to its tile; also fill g_cursor.
__global__ void scanC_kernel(int n, int nb) {
    __shared__ int s_off;
    const int tid = threadIdx.x;
    if (tid < 32) {
        int t = (tid < nb) ? g_btot[tid] : 0;
        int incl = t;
        #pragma unroll
        for (int off = 1; off < 32; off <<= 1) {
            int x = __shfl_up_sync(0xffffffffu, incl, off);
            if (tid >= off) incl += x;
        }
        int excl = incl - t;
        int my = __shfl_sync(0xffffffffu, excl, blockIdx.x);
        if (tid == 0) s_off = my;
    }
    __syncthreads();
    const int idx = blockIdx.x * 1024 + tid;
    if (idx < n) {
        int v = g_start[idx] + s_off;
        g_start[idx] = v;
        g_cursor[idx] = v;
    }
}

// Scatter: sort pairs by idx_i, writing precomputed meta + neighbor index.
__global__ void scatter_kernel(const int* __restrict__ pl,
                               const float* __restrict__ fc,
                               const float* __restrict__ rij,
                               int n_pairs) {
    int p = blockIdx.x * blockDim.x + threadIdx.x;
    if (p < n_pairs) {
        int i = pl[p];
        int j = pl[n_pairs + p];
        float f = __ldg(fc + p);
        float rx = __ldg(rij + 3 * p + 0);
        float ry = __ldg(rij + 3 * p + 1);
        float rz = __ldg(rij + 3 * p + 2);
        float inv = f * rsqrtf(rx * rx + ry * ry + rz * rz);
        int pos = atomicAdd(&g_cursor[i], 1);
        g_meta[pos] = make_float4(f, rx * inv, ry * inv, rz * inv);
        g_j[pos] = j;
    }
}

// ---------------------------------------------------------------------------
// Main fused kernel.
// smem: WT2 [128 f][64 gpair] ull  = pre-packed {W[2gp,f], W[2gp+1,f]}
//       SS  [8 warps][CHUNK][3][128] float
// ---------------------------------------------------------------------------
#define SS_PER_ATOM (3 * FDIM)
#define SS_PER_WARP (CHUNK * SS_PER_ATOM)
#define SMEM_MAIN (FDIM * 64 * 8 + WARPS_PER_BLOCK * SS_PER_WARP * 4)  // 90,112

__global__ void __launch_bounds__(MAIN_THREADS, 2)
main_kernel(const float* __restrict__ A,
            const float* __restrict__ W,
            const float* __restrict__ bvec,
            float*       __restrict__ out,
            int n_atoms)
{
    extern __shared__ char smem_raw[];
    ull*   WT2 = reinterpret_cast<ull*>(smem_raw);            // [128][64]
    float* SS  = reinterpret_cast<float*>(smem_raw + FDIM * 64 * 8);

    const int tid  = threadIdx.x;
    const int wid  = tid >> 5;
    const int lane = tid & 31;

    for (int idx = tid; idx < FDIM * 64; idx += MAIN_THREADS) {
        int f = idx >> 6, gp = idx & 63;
        WT2[f * 64 + gp] = pack2(__ldg(W + (2 * gp) * FDIM + f),
                                 __ldg(W + (2 * gp + 1) * FDIM + f));
    }
    __syncthreads();

    float* sw = SS + wid * SS_PER_WARP;
    const int fbase = 4 * lane;
    const int n_chunks = (n_atoms + CHUNK - 1) / CHUNK;
    const int wstep = gridDim.x * WARPS_PER_BLOCK;

    for (int ch = blockIdx.x * WARPS_PER_BLOCK + wid; ch < n_chunks; ch += wstep) {
        const int abase = ch * CHUNK;
        float degs[CHUNK];

        __syncwarp();   // previous chunk's matvec reads of sw are done

        // ================= gather: CHUNK atoms ============================
        #pragma unroll
        for (int a = 0; a < CHUNK; a++) {
            const int atom = abase + a;
            float4 racc = make_float4(0.f, 0.f, 0.f, 0.f);
            float4 sx = racc, sy = racc, sz = racc;
            degs[a] = 0.f;

            if (atom < n_atoms) {
                const int s0 = g_start[atom];
                const int s1 = g_start[atom + 1];
                degs[a] = (float)(s1 - s0);

                for (int base = s0; base < s1; base += 32) {
                    int m = s1 - base; if (m > 32) m = 32;
                    int jj = (lane < m) ? g_j[base + lane] : 0;

                    // depth-3 prefetch buffers (static indices only)
                    float4 ab0, ab1, ab2, mb0, mb1, mb2;
                    {
                        int j0 = __shfl_sync(0xffffffffu, jj, 0);
                        int j1 = __shfl_sync(0xffffffffu, jj, 1);
                        int j2 = __shfl_sync(0xffffffffu, jj, 2);
                        ab0 = *reinterpret_cast<const float4*>(A + (size_t)j0 * FDIM + fbase);
                        mb0 = g_meta[base];
                        if (m > 1) {
                            ab1 = *reinterpret_cast<const float4*>(A + (size_t)j1 * FDIM + fbase);
                            mb1 = g_meta[base + 1];
                        }
                        if (m > 2) {
                            ab2 = *reinterpret_cast<const float4*>(A + (size_t)j2 * FDIM + fbase);
                            mb2 = g_meta[base + 2];
                        }
                    }

                    int q = 0;
#define GSTEP(AB, MB)                                                          \
    {                                                                          \
        float4 av = AB;                                                        \
        float4 mm = MB;                                                        \
        if (q + 3 < m) {                                                       \
            int jn = __shfl_sync(0xffffffffu, jj, q + 3);                      \
            AB = *reinterpret_cast<const float4*>(A + (size_t)jn * FDIM + fbase); \
            MB = g_meta[base + q + 3];                                         \
        }                                                                      \
        racc.x = fmaf(mm.x, av.x, racc.x); racc.y = fmaf(mm.x, av.y, racc.y);  \
        racc.z = fmaf(mm.x, av.z, racc.z); racc.w = fmaf(mm.x, av.w, racc.w);  \
        sx.x = fmaf(mm.y, av.x, sx.x); sx.y = fmaf(mm.y, av.y, sx.y);          \
        sx.z = fmaf(mm.y, av.z, sx.z); sx.w = fmaf(mm.y, av.w, sx.w);          \
        sy.x = fmaf(mm.z, av.x, sy.x); sy.y = fmaf(mm.z, av.y, sy.y);          \
        sy.z = fmaf(mm.z, av.z, sy.z); sy.w = fmaf(mm.z, av.w, sy.w);          \
        sz.x = fmaf(mm.w, av.x, sz.x); sz.y = fmaf(mm.w, av.y, sz.y);          \
        sz.z = fmaf(mm.w, av.z, sz.z); sz.w = fmaf(mm.w, av.w, sz.w);          \
        q++;                                                                   \
    }
                    while (q < m) {
                        GSTEP(ab0, mb0);
                        if (q < m) GSTEP(ab1, mb1);
                        if (q < m) GSTEP(ab2, mb2);
                    }
#undef GSTEP
                }
                *reinterpret_cast<float4*>(
                    out + (size_t)atom * (2 * FDIM) + FDIM + fbase) = racc;
            }
            float* swa = sw + a * SS_PER_ATOM;
            *reinterpret_cast<float4*>(swa + 0 * FDIM + fbase) = sx;
            *reinterpret_cast<float4*>(swa + 1 * FDIM + fbase) = sy;
            *reinterpret_cast<float4*>(swa + 2 * FDIM + fbase) = sz;
        }
        __syncwarp();

        // ================= matvec: CHUNK atoms, packed f32x2 ===============
        ull acc[CHUNK * 6];
        #pragma unroll
        for (int k = 0; k < CHUNK * 6; k++) acc[k] = 0;

        const ull* wrow = WT2 + 2 * lane;

        #pragma unroll 2
        for (int f4 = 0; f4 < FDIM / 4; f4++) {
            ulonglong2 w0 = *reinterpret_cast<const ulonglong2*>(wrow + (4 * f4 + 0) * 64);
            ulonglong2 w1 = *reinterpret_cast<const ulonglong2*>(wrow + (4 * f4 + 1) * 64);
            ulonglong2 w2 = *reinterpret_cast<const ulonglong2*>(wrow + (4 * f4 + 2) * 64);
            ulonglong2 w3 = *reinterpret_cast<const ulonglong2*>(wrow + (4 * f4 + 3) * 64);
            #pragma unroll
            for (int a = 0; a < CHUNK; a++) {
                const float* swa = sw + a * SS_PER_ATOM + 4 * f4;
                float4 vx = *reinterpret_cast<const float4*>(swa);
                float4 vy = *reinterpret_cast<const float4*>(swa + FDIM);
                float4 vz = *reinterpret_cast<const float4*>(swa + 2 * FDIM);
                ull d;
                d = dup2(vx.x); FMA2(acc[a*6+0], d, w0.x); FMA2(acc[a*6+1], d, w0.y);
                d = dup2(vy.x); FMA2(acc[a*6+2], d, w0.x); FMA2(acc[a*6+3], d, w0.y);
                d = dup2(vz.x); FMA2(acc[a*6+4], d, w0.x); FMA2(acc[a*6+5], d, w0.y);
                d = dup2(vx.y); FMA2(acc[a*6+0], d, w1.x); FMA2(acc[a*6+1], d, w1.y);
                d = dup2(vy.y); FMA2(acc[a*6+2], d, w1.x); FMA2(acc[a*6+3], d, w1.y);
                d = dup2(vz.y); FMA2(acc[a*6+4], d, w1.x); FMA2(acc[a*6+5], d, w1.y);
                d = dup2(vx.z); FMA2(acc[a*6+0], d, w2.x); FMA2(acc[a*6+1], d, w2.y);
                d = dup2(vy.z); FMA2(acc[a*6+2], d, w2.x); FMA2(acc[a*6+3], d, w2.y);
                d = dup2(vz.z); FMA2(acc[a*6+4], d, w2.x); FMA2(acc[a*6+5], d, w2.y);
                d = dup2(vx.w); FMA2(acc[a*6+0], d, w3.x); FMA2(acc[a*6+1], d, w3.y);
                d = dup2(vy.w); FMA2(acc[a*6+2], d, w3.x); FMA2(acc[a*6+3], d, w3.y);
                d = dup2(vz.w); FMA2(acc[a*6+4], d, w3.x); FMA2(acc[a*6+5], d, w3.y);
            }
        }

        // ================= epilogue: bias + norm + store ===================
        float4 bb = __ldg(reinterpret_cast<const float4*>(bvec + fbase));
        #pragma unroll
        for (int a = 0; a < CHUNK; a++) {
            const int atom = abase + a;
            if (atom >= n_atoms) break;
            float tx[4], ty[4], tz[4];
            unpack2(acc[a*6+0], tx[0], tx[1]); unpack2(acc[a*6+1], tx[2], tx[3]);
            unpack2(acc[a*6+2], ty[0], ty[1]); unpack2(acc[a*6+3], ty[2], ty[3]);
            unpack2(acc[a*6+4], tz[0], tz[1]); unpack2(acc[a*6+5], tz[2], tz[3]);
            float bbv[4] = {bb.x, bb.y, bb.z, bb.w};
            float4 nrm;
            float* nv = &nrm.x;
            #pragma unroll
            for (int k = 0; k < 4; k++) {
                float db = degs[a] * bbv[k];
                float x = tx[k] + db;
                float y = ty[k] + db;
                float z = tz[k] + db;
                nv[k] = sqrtf(x * x + y * y + z * z + 1e-12f);
            }
            *reinterpret_cast<float4*>(out + (size_t)atom * (2 * FDIM) + fbase) = nrm;
        }
    }
}

// ---------------------------------------------------------------------------
extern "C" void kernel_launch(void* const* d_in, const int* in_sizes, int n_in,
                              void* d_out, int out_size) {
    const float* A   = (const float*)d_in[0];
    const int*   pl  = (const int*)d_in[1];
    const float* fc  = (const float*)d_in[2];
    const float* rij = (const float*)d_in[3];
    const float* W   = (const float*)d_in[4];
    const float* b   = (const float*)d_in[5];
    float* out = (float*)d_out;

    int n_atoms = in_sizes[0] / FDIM;
    int n_pairs = in_sizes[2];

    static int smem_set = 0;
    if (!smem_set) {
        cudaFuncSetAttribute(main_kernel,
                             cudaFuncAttributeMaxDynamicSharedMemorySize, SMEM_MAIN);
        smem_set = 1;
    }

    int pb = (n_pairs + 255) / 256;
    int n_scan = n_atoms + 1;
    int nb = (n_scan + 1023) / 1024;

    zero_counts_kernel<<<(n_scan + 255) / 256, 256>>>(n_atoms);
    hist_kernel<<<pb, 256>>>(pl, n_pairs);
    scanA_kernel<<<nb, 1024>>>(n_scan);
    scanC_kernel<<<nb, 1024>>>(n_scan, nb);
    scatter_kernel<<<pb, 256>>>(pl, fc, rij, n_pairs);
    main_kernel<<<MAIN_BLOCKS, MAIN_THREADS, SMEM_MAIN>>>(A, W, b, out, n_atoms);
}

// round 15
// speedup vs baseline: 1.5079x; 1.5079x over previous
#include <cuda_runtime.h>
#include <cuda_bf16.h>

// ---------------------------------------------------------------------------
// AIMNet2 interaction module — fused per-atom formulation.
//
//   radial[i]   = Σ_{p∈i} f_p * A[j_p]
//   s[i,c,:]    = Σ_{p∈i} (f_p u[p,c]) * A[j_p]
//   vec[i,c,:]  = W @ s[i,c,:] + deg(i)*b
//   out[i]      = [ sqrt(Σ_c vec² + 1e-12), radial ]
//
// Pipeline: hist -> parallel 2-phase scan -> scatter (sorted meta
//   {f, f*ux, f*uy, f*uz} + j) -> fused kernel (R7 skeleton; gather uses
//   unrolled groups of 8 pairs with all loads issued up front: MLP=16).
// ---------------------------------------------------------------------------

#define FDIM 128
#define WT_S 132
#define S2_S 132
#define MAX_ATOMS 20480
#define MAX_PAIRS 393216
#define MAIN_BLOCKS 296
#define WARPS_PER_BLOCK 8
#define MAIN_THREADS (WARPS_PER_BLOCK * 32)
#define MAIN_WARPS (MAIN_BLOCKS * WARPS_PER_BLOCK)

typedef unsigned long long ull;

__device__ int g_count[MAX_ATOMS + 1];
__device__ int g_start[MAX_ATOMS + 1];
__device__ int g_cursor[MAX_ATOMS + 1];
__device__ int g_btot[64];
__device__ int g_j[MAX_PAIRS];
__device__ __align__(16) float4 g_meta[MAX_PAIRS];   // {f, f*ux, f*uy, f*uz}

__device__ __forceinline__ ull dup2(float v) {
    ull d; asm("mov.b64 %0, {%1, %1};" : "=l"(d) : "f"(v)); return d;
}
__device__ __forceinline__ ull pack2(float lo, float hi) {
    ull d; asm("mov.b64 %0, {%1, %2};" : "=l"(d) : "f"(lo), "f"(hi)); return d;
}
__device__ __forceinline__ void unpack2(ull v, float& lo, float& hi) {
    asm("mov.b64 {%0, %1}, %2;" : "=f"(lo), "=f"(hi) : "l"(v));
}
#define FMA2(acc, a, b) \
    asm("fma.rn.f32x2 %0, %1, %2, %0;" : "+l"(acc) : "l"(a), "l"(b))

// ---------------------------------------------------------------------------
__global__ void zero_counts_kernel(int n_atoms) {
    int i = blockIdx.x * blockDim.x + threadIdx.x;
    if (i <= n_atoms) g_count[i] = 0;
}

__global__ void hist_kernel(const int* __restrict__ pl, int n_pairs) {
    int p = blockIdx.x * blockDim.x + threadIdx.x;
    if (p < n_pairs) atomicAdd(&g_count[pl[p]], 1);
}

// Phase A: per-block tile scan -> local-exclusive g_start, block total g_btot.
__global__ void scanA_kernel(int n) {
    __shared__ int wsum[32];
    const int tid = threadIdx.x;
    const int lane = tid & 31;
    const int w = tid >> 5;
    const int idx = blockIdx.x * 1024 + tid;
    int v = (idx < n) ? g_count[idx] : 0;
    int incl = v;
    #pragma unroll
    for (int off = 1; off < 32; off <<= 1) {
        int t = __shfl_up_sync(0xffffffffu, incl, off);
        if (lane >= off) incl += t;
    }
    if (lane == 31) wsum[w] = incl;
    __syncthreads();
    if (w == 0) {
        int s = wsum[lane];
        int i2 = s;
        #pragma unroll
        for (int off = 1; off < 32; off <<= 1) {
            int t = __shfl_up_sync(0xffffffffu, i2, off);
            if (lane >= off) i2 += t;
        }
        wsum[lane] = i2 - s;
    }
    __syncthreads();
    int excl = wsum[w] + incl - v;
    if (idx < n) g_start[idx] = excl;
    if (tid == 1023) g_btot[blockIdx.x] = wsum[w] + incl;
}

// Phase B/C fused: warp-scan of block totals, add offset, fill g_cursor.
__global__ void scanC_kernel(int n, int nb) {
    __shared__ int s_off;
    const int tid = threadIdx.x;
    if (tid < 32) {
        int t = (tid < nb) ? g_btot[tid] : 0;
        int incl = t;
        #pragma unroll
        for (int off = 1; off < 32; off <<= 1) {
            int x = __shfl_up_sync(0xffffffffu, incl, off);
            if (tid >= off) incl += x;
        }
        int excl = incl - t;
        int my = __shfl_sync(0xffffffffu, excl, blockIdx.x);
        if (tid == 0) s_off = my;
    }
    __syncthreads();
    const int idx = blockIdx.x * 1024 + tid;
    if (idx < n) {
        int v = g_start[idx] + s_off;
        g_start[idx] = v;
        g_cursor[idx] = v;
    }
}

// Scatter: sort pairs by idx_i, precomputing meta {f, f*ux, f*uy, f*uz}.
__global__ void scatter_kernel(const int* __restrict__ pl,
                               const float* __restrict__ fc,
                               const float* __restrict__ rij,
                               int n_pairs) {
    int p = blockIdx.x * blockDim.x + threadIdx.x;
    if (p < n_pairs) {
        int i = pl[p];
        int j = pl[n_pairs + p];
        float f = __ldg(fc + p);
        float rx = __ldg(rij + 3 * p + 0);
        float ry = __ldg(rij + 3 * p + 1);
        float rz = __ldg(rij + 3 * p + 2);
        float inv = f * rsqrtf(rx * rx + ry * ry + rz * rz);
        int pos = atomicAdd(&g_cursor[i], 1);
        g_meta[pos] = make_float4(f, rx * inv, ry * inv, rz * inv);
        g_j[pos] = j;
    }
}

// ---------------------------------------------------------------------------
// Gather group of up to 8 pairs: issue all 16 loads, then 128 FMAs.
// FULL=true: unguarded. FULL=false: indices clamped, OOB meta zeroed.
// ---------------------------------------------------------------------------
template<bool FULL>
__device__ __forceinline__ void gather_group(
    const float* __restrict__ A, int fbase, int base, int q0, int m, int jj,
    float4& racc, float4& sx, float4& sy, float4& sz)
{
    float4 av[8], mv[8];
    #pragma unroll
    for (int k = 0; k < 8; k++) {
        int qk = q0 + k;
        int kk = FULL ? qk : (qk < m ? qk : 0);
        int j = __shfl_sync(0xffffffffu, jj, kk);
        av[k] = *reinterpret_cast<const float4*>(A + (size_t)j * FDIM + fbase);
        mv[k] = g_meta[base + kk];
        if (!FULL && qk >= m) mv[k] = make_float4(0.f, 0.f, 0.f, 0.f);
    }
    #pragma unroll
    for (int k = 0; k < 8; k++) {
        float4 av_ = av[k], mm = mv[k];
        racc.x = fmaf(mm.x, av_.x, racc.x); racc.y = fmaf(mm.x, av_.y, racc.y);
        racc.z = fmaf(mm.x, av_.z, racc.z); racc.w = fmaf(mm.x, av_.w, racc.w);
        sx.x = fmaf(mm.y, av_.x, sx.x); sx.y = fmaf(mm.y, av_.y, sx.y);
        sx.z = fmaf(mm.y, av_.z, sx.z); sx.w = fmaf(mm.y, av_.w, sx.w);
        sy.x = fmaf(mm.z, av_.x, sy.x); sy.y = fmaf(mm.z, av_.y, sy.y);
        sy.z = fmaf(mm.z, av_.z, sy.z); sy.w = fmaf(mm.z, av_.w, sy.w);
        sz.x = fmaf(mm.w, av_.x, sz.x); sz.y = fmaf(mm.w, av_.y, sz.y);
        sz.z = fmaf(mm.w, av_.z, sz.z); sz.w = fmaf(mm.w, av_.w, sz.w);
    }
}

// ---------------------------------------------------------------------------
// Main fused kernel (R7 skeleton: warp = 1 atom per grid-stride step).
// smem: WT [128][132] float (W^T) + S2 [8 warps][3][132] ull (dup2-staged s).
// ---------------------------------------------------------------------------
#define SMEM_MAIN (FDIM * WT_S * 4 + WARPS_PER_BLOCK * 3 * S2_S * 8)  // 92,928

__global__ void __launch_bounds__(MAIN_THREADS, 2)
main_kernel(const float* __restrict__ A,
            const float* __restrict__ W,
            const float* __restrict__ bvec,
            float*       __restrict__ out,
            int n_atoms)
{
    extern __shared__ float smem[];
    float* WT = smem;                               // [128][WT_S]: WT[f][g]=W[g][f]
    ull* S2   = (ull*)(smem + FDIM * WT_S);         // [8][3][S2_S]

    const int tid  = threadIdx.x;
    const int wid  = tid >> 5;
    const int lane = tid & 31;

    for (int idx = tid; idx < FDIM * FDIM; idx += MAIN_THREADS) {
        int g = idx >> 7, f = idx & (FDIM - 1);
        WT[f * WT_S + g] = W[idx];
    }
    __syncthreads();

    ull* s2w = S2 + wid * 3 * S2_S;
    const int fbase = 4 * lane;

    for (int atom = blockIdx.x * WARPS_PER_BLOCK + wid; atom < n_atoms;
         atom += MAIN_WARPS) {
        const int s0 = g_start[atom];
        const int s1 = g_start[atom + 1];

        // ================= gather: grouped, high-MLP =======================
        float4 racc = make_float4(0.f, 0.f, 0.f, 0.f);
        float4 sx = racc, sy = racc, sz = racc;

        for (int base = s0; base < s1; base += 32) {
            int m = s1 - base; if (m > 32) m = 32;
            int jj = (lane < m) ? g_j[base + lane] : 0;
            int q0 = 0;
            for (; q0 + 8 <= m; q0 += 8)
                gather_group<true>(A, fbase, base, q0, m, jj, racc, sx, sy, sz);
            if (q0 < m)
                gather_group<false>(A, fbase, base, q0, m, jj, racc, sx, sy, sz);
        }

        // radial half of the output
        *reinterpret_cast<float4*>(
            out + (size_t)atom * (2 * FDIM) + FDIM + fbase) = racc;

        // ---- stage s duplicated ({v,v}) for packed broadcast reads ----
        __syncwarp();   // prior atom's matvec reads of s2w are done
        s2w[0 * S2_S + fbase + 0] = dup2(sx.x);
        s2w[0 * S2_S + fbase + 1] = dup2(sx.y);
        s2w[0 * S2_S + fbase + 2] = dup2(sx.z);
        s2w[0 * S2_S + fbase + 3] = dup2(sx.w);
        s2w[1 * S2_S + fbase + 0] = dup2(sy.x);
        s2w[1 * S2_S + fbase + 1] = dup2(sy.y);
        s2w[1 * S2_S + fbase + 2] = dup2(sy.z);
        s2w[1 * S2_S + fbase + 3] = dup2(sy.w);
        s2w[2 * S2_S + fbase + 0] = dup2(sz.x);
        s2w[2 * S2_S + fbase + 1] = dup2(sz.y);
        s2w[2 * S2_S + fbase + 2] = dup2(sz.z);
        s2w[2 * S2_S + fbase + 3] = dup2(sz.w);
        __syncwarp();

        // ================= matvec: packed f32x2 (R7-proven) ================
        ull a00 = 0, a01 = 0, a10 = 0, a11 = 0, a20 = 0, a21 = 0;
        #pragma unroll 8
        for (int f = 0; f < FDIM; f++) {
            float4 Wv = *reinterpret_cast<const float4*>(WT + f * WT_S + fbase);
            ull wp0 = pack2(Wv.x, Wv.y);
            ull wp1 = pack2(Wv.z, Wv.w);
            ull sb0 = s2w[0 * S2_S + f];
            ull sb1 = s2w[1 * S2_S + f];
            ull sb2 = s2w[2 * S2_S + f];
            FMA2(a00, sb0, wp0); FMA2(a01, sb0, wp1);
            FMA2(a10, sb1, wp0); FMA2(a11, sb1, wp1);
            FMA2(a20, sb2, wp0); FMA2(a21, sb2, wp1);
        }

        // ================= epilogue: bias + norm + store ===================
        float tx[4], ty[4], tz[4];
        unpack2(a00, tx[0], tx[1]); unpack2(a01, tx[2], tx[3]);
        unpack2(a10, ty[0], ty[1]); unpack2(a11, ty[2], ty[3]);
        unpack2(a20, tz[0], tz[1]); unpack2(a21, tz[2], tz[3]);

        float deg = (float)(s1 - s0);
        float4 bb = __ldg(reinterpret_cast<const float4*>(bvec + fbase));
        float bbv[4] = {bb.x, bb.y, bb.z, bb.w};

        float4 nrm;
        float* nv = &nrm.x;
        #pragma unroll
        for (int k = 0; k < 4; k++) {
            float db = deg * bbv[k];
            float x = tx[k] + db;
            float y = ty[k] + db;
            float z = tz[k] + db;
            nv[k] = sqrtf(x * x + y * y + z * z + 1e-12f);
        }
        *reinterpret_cast<float4*>(out + (size_t)atom * (2 * FDIM) + fbase) = nrm;
    }
}

// ---------------------------------------------------------------------------
extern "C" void kernel_launch(void* const* d_in, const int* in_sizes, int n_in,
                              void* d_out, int out_size) {
    const float* A   = (const float*)d_in[0];
    const int*   pl  = (const int*)d_in[1];
    const float* fc  = (const float*)d_in[2];
    const float* rij = (const float*)d_in[3];
    const float* W   = (const float*)d_in[4];
    const float* b   = (const float*)d_in[5];
    float* out = (float*)d_out;

    int n_atoms = in_sizes[0] / FDIM;
    int n_pairs = in_sizes[2];

    static int smem_set = 0;
    if (!smem_set) {
        cudaFuncSetAttribute(main_kernel,
                             cudaFuncAttributeMaxDynamicSharedMemorySize, SMEM_MAIN);
        smem_set = 1;
    }

    int pb = (n_pairs + 255) / 256;
    int n_scan = n_atoms + 1;
    int nb = (n_scan + 1023) / 1024;

    zero_counts_kernel<<<(n_scan + 255) / 256, 256>>>(n_atoms);
    hist_kernel<<<pb, 256>>>(pl, n_pairs);
    scanA_kernel<<<nb, 1024>>>(n_scan);
    scanC_kernel<<<nb, 1024>>>(n_scan, nb);
    scatter_kernel<<<pb, 256>>>(pl, fc, rij, n_pairs);
    main_kernel<<<MAIN_BLOCKS, MAIN_THREADS, SMEM_MAIN>>>(A, W, b, out, n_atoms);
}